// round 4
// baseline (speedup 1.0000x reference)
#include <cuda_runtime.h>
#include <cstdint>

#define NBLK 128

// ---------------- scratch (no mallocs allowed) ----------------
__device__ float g_keys[64 * 256 * 1024];      // memory @ W_mem           64MB
__device__ float g_MW[64 * 256 * 1024];        // memory @ W_attn[1024:]   64MB
__device__ float g_attn_all[64 * 256 * 1024];  // all attn_new outputs     64MB
__device__ float g_q2[64 * 2048];              // [q | h@W_attn_top]
__device__ float g_h[2][64 * 1024];
__device__ float g_c[64 * 1024];
__device__ float g_attn[64 * 1024];
__device__ float g_scores[64 * 256];
__device__ unsigned g_cnt;
__device__ volatile unsigned g_gen;

// ---------------- helpers ----------------
__device__ __forceinline__ unsigned long long pack2dup(float x) {
    unsigned long long r;
    asm("mov.b64 %0, {%1, %1};" : "=l"(r) : "f"(x));
    return r;
}
__device__ __forceinline__ float2 unpack2(unsigned long long v) {
    float2 r;
    asm("mov.b64 {%0, %1}, %2;" : "=f"(r.x), "=f"(r.y) : "l"(v));
    return r;
}
__device__ __forceinline__ void fma2(unsigned long long& acc, unsigned long long a,
                                     unsigned long long b) {
    asm("fma.rn.f32x2 %0, %1, %2, %0;" : "+l"(acc) : "l"(a), "l"(b));
}
__device__ __forceinline__ float tanh_ap(float x) {
    float y;
    asm("tanh.approx.f32 %0, %1;" : "=f"(y) : "f"(x));
    return y;
}
__device__ __forceinline__ float sigf(float x) { return 1.0f / (1.0f + __expf(-x)); }

// ---------------- software grid barrier ----------------
__device__ __forceinline__ void gsync() {
    __syncthreads();
    if (threadIdx.x == 0) {
        unsigned g = g_gen;
        __threadfence();
        if (atomicAdd(&g_cnt, 1u) == (unsigned)(NBLK - 1)) {
            g_cnt = 0;
            __threadfence();
            g_gen = g + 1;
        } else {
            while (g_gen == g) { __nanosleep(64); }
        }
        __threadfence();
    }
    __syncthreads();
}

// ---------------- big GEMM: C[M,N] = A[M,K] @ B[K,N] (+bias) ----------------
#define BM 128
#define BN 128
#define BKK 16
__global__ __launch_bounds__(256, 1) void gemm_f32(
    const float* __restrict__ A, const float* __restrict__ Bm,
    const float* __restrict__ bias, float* __restrict__ C, int M, int N, int K)
{
    __shared__ __align__(16) float As[BKK][BM + 4];
    __shared__ __align__(16) float Bs[BKK][BN + 4];

    int tid = threadIdx.x;
    int tn = (tid & 15) * 8;
    int tm = (tid >> 4) * 8;
    int a_m = tid >> 2;
    int a_k = (tid & 3) * 4;
    int b_k = tid >> 5;
    int b_n = (tid & 31) * 4;

    const float* Aptr = A + (size_t)(blockIdx.y * BM) * K;
    const float* Bptr = Bm + blockIdx.x * BN;

    unsigned long long acc[8][4];
#pragma unroll
    for (int i = 0; i < 8; ++i)
#pragma unroll
        for (int j = 0; j < 4; ++j) acc[i][j] = 0ull;

    for (int k0 = 0; k0 < K; k0 += BKK) {
#pragma unroll
        for (int i = 0; i < 2; ++i) {
            int m = a_m + i * 64;
            float4 v = *(const float4*)(Aptr + (size_t)m * K + k0 + a_k);
            As[a_k + 0][m] = v.x;
            As[a_k + 1][m] = v.y;
            As[a_k + 2][m] = v.z;
            As[a_k + 3][m] = v.w;
        }
#pragma unroll
        for (int i = 0; i < 2; ++i) {
            int kk = b_k + i * 8;
            float4 v = *(const float4*)(Bptr + (size_t)(k0 + kk) * N + b_n);
            *(float4*)&Bs[kk][b_n] = v;
        }
        __syncthreads();
#pragma unroll
        for (int kk = 0; kk < BKK; ++kk) {
            float4 a0 = *(const float4*)&As[kk][tm];
            float4 a1 = *(const float4*)&As[kk][tm + 4];
            ulonglong2 bb0 = *(const ulonglong2*)&Bs[kk][tn];
            ulonglong2 bb1 = *(const ulonglong2*)&Bs[kk][tn + 4];
            float av[8] = {a0.x, a0.y, a0.z, a0.w, a1.x, a1.y, a1.z, a1.w};
            unsigned long long bv[4] = {bb0.x, bb0.y, bb1.x, bb1.y};
#pragma unroll
            for (int i = 0; i < 8; ++i) {
                unsigned long long a2 = pack2dup(av[i]);
#pragma unroll
                for (int j = 0; j < 4; ++j) fma2(acc[i][j], a2, bv[j]);
            }
        }
        __syncthreads();
    }

#pragma unroll
    for (int i = 0; i < 8; ++i) {
        int m = blockIdx.y * BM + tm + i;
        int n0 = blockIdx.x * BN + tn;
        float o[8];
#pragma unroll
        for (int j = 0; j < 4; ++j) {
            float2 v = unpack2(acc[i][j]);
            o[2 * j] = v.x;
            o[2 * j + 1] = v.y;
        }
        if (bias) {
#pragma unroll
            for (int j = 0; j < 8; ++j) o[j] += bias[n0 + j];
        }
        float* cp = C + (size_t)m * N + n0;
        *(float4*)cp = make_float4(o[0], o[1], o[2], o[3]);
        *(float4*)(cp + 4) = make_float4(o[4], o[5], o[6], o[7]);
    }
}

// ---------------- persistent megakernel: all 256 decoder steps ----------------
__global__ __launch_bounds__(256, 1) void mega(
    const float* __restrict__ dec, const float* __restrict__ h0,
    const float* __restrict__ c0, const float* __restrict__ Wl,
    const float* __restrict__ Ul, const float* __restrict__ bl,
    const float* __restrict__ Wq, const float* __restrict__ Wa,
    const float* __restrict__ va, const int* __restrict__ mlen)
{
    __shared__ __align__(16) float sA[2048];   // k-chunk staging (pair-interleaved)
    __shared__ float zs[128][17];              // z exchange for gate fusion
    __shared__ __align__(16) float qv[1024];
    __shared__ __align__(16) float vv[1024];
    __shared__ float ps[256];
    __shared__ float red[256];

    const int tid = threadIdx.x, bid = blockIdx.x;
    const int w = tid >> 5, lane = tid & 31;
    unsigned long long* sA2 = (unsigned long long*)sA;

    // init state (replaces memcpy/memset nodes)
    for (int i = bid * 256 + tid; i < 64 * 1024; i += NBLK * 256) {
        g_h[0][i] = h0[i];
        g_c[i] = c0[i];
        g_attn[i] = 0.f;
    }
    for (int i = tid; i < 1024; i += 256) vv[i] = va[i];
    gsync();

    // Z: 4 b-tiles(16) x 32 u-tiles(32); warp = (gate, b-half); lane = u-col
    const int z_ut = bid & 31, z_bt = bid >> 5;
    const int z_cg = w & 3, z_bg = w >> 2;
    const float* z_wl = Wl + (size_t)z_cg * 1024 + z_ut * 32 + lane;
    const float* z_wu = Ul + (size_t)z_cg * 1024 + z_ut * 32 + lane;
    const float z_bias = bl[z_cg * 1024 + z_ut * 32 + lane];
    // Q: 8 b-tiles(8) x 16 n-tiles(128); n = [q | h@Wa_top]
    const int q_nt = bid & 15, q_bt = bid >> 4;
    const int q_cg = w & 3, q_bg = w >> 2;
    const int q_n = q_nt * 128 + q_cg * 32 + lane;
    const float* q_wcol = (q_n < 1024) ? (Wq + q_n) : (Wa + (q_n - 1024));
    // S / C: 64 b x 2 halves
    const int s_b = bid >> 1, s_st = bid & 1;

    for (int t = 0; t < 256; ++t) {
        const int cur = t & 1, nxt = cur ^ 1;
        const float* hcur = g_h[cur];
        float* hnxt = g_h[nxt];

        // ================= Z phase: z = [x_t|attn|h] @ [Wl;Ul] + gates =====
        unsigned long long acc[4] = {0ull, 0ull, 0ull, 0ull};
        for (int k0 = 0; k0 < 3072; k0 += 128) {
#pragma unroll
            for (int j = 0; j < 8; ++j) {
                int idx = j * 256 + tid;
                int row = idx >> 7, kl = idx & 127;
                int k = k0 + kl;
                int bg = z_bt * 16 + row;
                float v;
                if (k < 1024)       v = dec[((size_t)bg * 256 + t) * 1024 + k];
                else if (k < 2048)  v = g_attn[bg * 1024 + (k - 1024)];
                else                v = hcur[bg * 1024 + (k - 2048)];
                sA[(((row >> 1) * 128 + kl) << 1) | (row & 1)] = v;
            }
            __syncthreads();
            const float* wc = (k0 < 2048) ? (z_wl + (size_t)k0 * 4096)
                                          : (z_wu + (size_t)(k0 - 2048) * 4096);
#pragma unroll 8
            for (int kk = 0; kk < 128; kk += 2) {
                unsigned long long w0 = pack2dup(wc[(size_t)kk * 4096]);
                unsigned long long w1 = pack2dup(wc[(size_t)(kk + 1) * 4096]);
#pragma unroll
                for (int pi = 0; pi < 4; ++pi) {
                    ulonglong2 a = *(const ulonglong2*)&sA2[(z_bg * 4 + pi) * 128 + kk];
                    fma2(acc[pi], w0, a.x);
                    fma2(acc[pi], w1, a.y);
                }
            }
            __syncthreads();
        }
        {
            int c = z_cg * 32 + lane;
#pragma unroll
            for (int pi = 0; pi < 4; ++pi) {
                float2 v = unpack2(acc[pi]);
                int b2 = (z_bg * 4 + pi) * 2;
                zs[c][b2] = v.x + z_bias;
                zs[c][b2 + 1] = v.y + z_bias;
            }
        }
        __syncthreads();
        for (int e = tid; e < 512; e += 256) {
            int b2 = e >> 5, up = e & 31;
            float zi = zs[up][b2], zf = zs[32 + up][b2];
            float zg = zs[64 + up][b2], zo = zs[96 + up][b2];
            int idx = (z_bt * 16 + b2) * 1024 + z_ut * 32 + up;
            float cc = sigf(zf) * g_c[idx] + sigf(zi) * tanhf(zg);
            g_c[idx] = cc;
            hnxt[idx] = sigf(zo) * tanhf(cc);
        }
        gsync();

        // ================= Q phase: [q|hWa] = h_new @ [Wq|Wa_top] ==========
        unsigned long long qa[2] = {0ull, 0ull};
        for (int k0 = 0; k0 < 1024; k0 += 128) {
#pragma unroll
            for (int j = 0; j < 4; ++j) {
                int idx = j * 256 + tid;
                int row = idx >> 7, kl = idx & 127;
                sA[(((row >> 1) * 128 + kl) << 1) | (row & 1)] =
                    hnxt[(q_bt * 8 + row) * 1024 + k0 + kl];
            }
            __syncthreads();
            const float* wc = q_wcol + (size_t)k0 * 1024;
#pragma unroll 8
            for (int kk = 0; kk < 128; kk += 2) {
                unsigned long long w0 = pack2dup(wc[(size_t)kk * 1024]);
                unsigned long long w1 = pack2dup(wc[(size_t)(kk + 1) * 1024]);
#pragma unroll
                for (int pi = 0; pi < 2; ++pi) {
                    ulonglong2 a = *(const ulonglong2*)&sA2[(q_bg * 2 + pi) * 128 + kk];
                    fma2(qa[pi], w0, a.x);
                    fma2(qa[pi], w1, a.y);
                }
            }
            __syncthreads();
        }
#pragma unroll
        for (int pi = 0; pi < 2; ++pi) {
            float2 v = unpack2(qa[pi]);
            int b2 = q_bt * 8 + (q_bg * 2 + pi) * 2;
            g_q2[b2 * 2048 + q_n] = v.x;
            g_q2[(b2 + 1) * 2048 + q_n] = v.y;
        }
        gsync();

        // ================= S phase: masked additive scores =================
        for (int i = tid; i < 1024; i += 256) qv[i] = g_q2[s_b * 2048 + i];
        __syncthreads();
        {
            int len = mlen[s_b];
#pragma unroll
            for (int i = 0; i < 16; ++i) {
                int s = s_st * 128 + w * 16 + i;
                float sc = -1e9f;
                if (s < len) {
                    const float* kp = g_keys + ((size_t)s_b * 256 + s) * 1024;
                    float a = 0.f;
#pragma unroll
                    for (int j2 = 0; j2 < 8; ++j2) {
                        int u = lane * 4 + j2 * 128;
                        float4 kv = *(const float4*)(kp + u);
                        float4 qf = *(const float4*)(qv + u);
                        float4 vf = *(const float4*)(vv + u);
                        a += tanh_ap(kv.x + qf.x) * vf.x;
                        a += tanh_ap(kv.y + qf.y) * vf.y;
                        a += tanh_ap(kv.z + qf.z) * vf.z;
                        a += tanh_ap(kv.w + qf.w) * vf.w;
                    }
#pragma unroll
                    for (int off = 16; off; off >>= 1)
                        a += __shfl_xor_sync(0xffffffffu, a, off);
                    sc = a;
                }
                if (lane == 0) g_scores[s_b * 256 + s] = sc;
            }
        }
        gsync();

        // ========== C phase: softmax + (align@MW) + hWa -> attn_new ========
        {
            int len = mlen[s_b];
            float sc = g_scores[s_b * 256 + tid];
            red[tid] = sc;
            __syncthreads();
            for (int st = 128; st; st >>= 1) {
                if (tid < st) red[tid] = fmaxf(red[tid], red[tid + st]);
                __syncthreads();
            }
            float m = red[0];
            __syncthreads();
            float e = __expf(sc - m);
            red[tid] = e;
            __syncthreads();
            for (int st = 128; st; st >>= 1) {
                if (tid < st) red[tid] += red[tid + st];
                __syncthreads();
            }
            float inv = 1.f / red[0];
            __syncthreads();
            ps[tid] = e * inv;
            __syncthreads();

            int u0 = s_st * 512 + tid * 2;
            const float* mwp = g_MW + (size_t)s_b * 256 * 1024 + u0;
            unsigned long long ca = 0ull, cb = 0ull;
            int s = 0;
            for (; s + 1 < len; s += 2) {
                fma2(ca, pack2dup(ps[s]),
                     *(const unsigned long long*)(mwp + (size_t)s * 1024));
                fma2(cb, pack2dup(ps[s + 1]),
                     *(const unsigned long long*)(mwp + (size_t)(s + 1) * 1024));
            }
            if (s < len)
                fma2(ca, pack2dup(ps[s]),
                     *(const unsigned long long*)(mwp + (size_t)s * 1024));
            float2 v0 = unpack2(ca), v1 = unpack2(cb);
            float2 hw = *(const float2*)&g_q2[s_b * 2048 + 1024 + u0];
            float a0 = v0.x + v1.x + hw.x;
            float a1 = v0.y + v1.y + hw.y;
            int ai = s_b * 1024 + u0;
            g_attn[ai] = a0;
            g_attn[ai + 1] = a1;
            float* ao = g_attn_all + ((size_t)s_b * 256 + t) * 1024 + u0;
            ao[0] = a0;
            ao[1] = a1;
        }
        gsync();
    }
}

// ---------------- launch: 4 graph nodes ----------------
extern "C" void kernel_launch(void* const* d_in, const int* in_sizes, int n_in,
                              void* d_out, int out_size)
{
    const float* memory  = (const float*)d_in[0];
    const float* dec     = (const float*)d_in[1];
    const float* h0      = (const float*)d_in[2];
    const float* c0      = (const float*)d_in[3];
    const float* W_lstm  = (const float*)d_in[4];
    const float* U_lstm  = (const float*)d_in[5];
    const float* b_lstm  = (const float*)d_in[6];
    const float* W_mem   = (const float*)d_in[7];
    const float* W_query = (const float*)d_in[8];
    const float* v_att   = (const float*)d_in[9];
    const float* W_attn  = (const float*)d_in[10];
    const float* W_out   = (const float*)d_in[11];
    const float* b_out   = (const float*)d_in[12];
    const int*   mem_len = (const int*)d_in[13];
    float* out = (float*)d_out;

    void* p;
    cudaGetSymbolAddress(&p, g_keys);     float* keys = (float*)p;
    cudaGetSymbolAddress(&p, g_MW);       float* MW = (float*)p;
    cudaGetSymbolAddress(&p, g_attn_all); float* attn_all = (float*)p;

    // keys = memory @ W_mem ; MW = memory @ W_attn[1024:, :]
    gemm_f32<<<dim3(8, 128), 256>>>(memory, W_mem, nullptr, keys, 16384, 1024, 1024);
    gemm_f32<<<dim3(8, 128), 256>>>(memory, W_attn + 1024 * 1024, nullptr, MW,
                                    16384, 1024, 1024);
    // all 256 decoder steps
    mega<<<NBLK, 256>>>(dec, h0, c0, W_lstm, U_lstm, b_lstm, W_query, W_attn,
                        v_att, mem_len);
    // out = attn_all @ W_out + b_out
    gemm_f32<<<dim3(8, 128), 256>>>(attn_all, W_out, b_out, out, 16384, 1024, 1024);
}